// round 15
// baseline (speedup 1.0000x reference)
#include <cuda_runtime.h>
#include <cuda_bf16.h>
#include <cstdint>
#include <math.h>

#define Bn   16
#define Cn   256
#define MIDn 128
#define Hn   128
#define Wn   128
#define HWn  (Hn*Wn)
#define ST   72

// ================= warp-MMA helpers =================
__device__ __forceinline__ uint32_t smem_u32(const void* p) {
    uint32_t a;
    asm("{ .reg .u64 t; cvta.to.shared.u64 t, %1; cvt.u32.u64 %0, t; }" : "=r"(a) : "l"(p));
    return a;
}
__device__ __forceinline__ void ldsm_x4(uint32_t* r, uint32_t addr) {
    asm volatile("ldmatrix.sync.aligned.m8n8.x4.shared.b16 {%0,%1,%2,%3}, [%4];"
                 : "=r"(r[0]), "=r"(r[1]), "=r"(r[2]), "=r"(r[3]) : "r"(addr));
}
__device__ __forceinline__ void mma_bf16(float* d, const uint32_t* a, uint32_t b0, uint32_t b1) {
    asm volatile("mma.sync.aligned.m16n8k16.row.col.f32.bf16.bf16.f32 "
                 "{%0,%1,%2,%3}, {%4,%5,%6,%7}, {%8,%9}, {%0,%1,%2,%3};"
                 : "+f"(d[0]), "+f"(d[1]), "+f"(d[2]), "+f"(d[3])
                 : "r"(a[0]), "r"(a[1]), "r"(a[2]), "r"(a[3]), "r"(b0), "r"(b1));
}
__device__ __forceinline__ void cp16(uint32_t saddr, const void* g) {
    asm volatile("cp.async.cg.shared.global [%0], [%1], 16;" :: "r"(saddr), "l"(g) : "memory");
}
#define CP_COMMIT() asm volatile("cp.async.commit_group;" ::: "memory")
#define CP_WAIT0()  asm volatile("cp.async.wait_group 0;" ::: "memory")
#define CP_WAIT1()  asm volatile("cp.async.wait_group 1;" ::: "memory")
__device__ __forceinline__ float leaky(float v) { return v >= 0.f ? v : 0.2f * v; }
__device__ __forceinline__ uint32_t pack_hi(float a, float b) {
    __nv_bfloat16 h0 = __float2bfloat16(a), h1 = __float2bfloat16(b);
    return (uint32_t)__bfloat16_as_ushort(h0) | ((uint32_t)__bfloat16_as_ushort(h1) << 16);
}
__device__ __forceinline__ uint32_t pack_lo(float a, float b) {
    __nv_bfloat16 h0 = __float2bfloat16(a), h1 = __float2bfloat16(b);
    __nv_bfloat16 l0 = __float2bfloat16(a - __bfloat162float(h0));
    __nv_bfloat16 l1 = __float2bfloat16(b - __bfloat162float(h1));
    return (uint32_t)__bfloat16_as_ushort(l0) | ((uint32_t)__bfloat16_as_ushort(l1) << 16);
}

// ================= scratch =================
__device__ uint4 g_w1p[9 * 8 * 16 * 2 * 32];        // conv1 B-fragments
__device__ __nv_bfloat16 g_w2h[256 * 128];
__device__ __nv_bfloat16 g_w2l[256 * 128];
__device__ __nv_bfloat16 g_h1h[(size_t)Bn * HWn * MIDn];
__device__ __nv_bfloat16 g_h1l[(size_t)Bn * HWn * MIDn];
__device__ __nv_bfloat16 g_xch[(size_t)Bn * HWn * Cn];
__device__ __nv_bfloat16 g_xcl[(size_t)Bn * HWn * Cn];
__device__ float g_ppart[Bn * 64 * 2 * 128];
__device__ float g_pooled[Bn * Cn];
__device__ __nv_bfloat16 g_scoreH[(size_t)Bn * Cn * Cn];
__device__ __nv_bfloat16 g_scoreL[(size_t)Bn * Cn * Cn];

// ---------------- dummy (keeps ncu's sampled launch index on conv1) ----------------
__global__ void dummy_kernel() {}

// ---------------- kernel 0: weight prep ----------------
__global__ void prep_kernel(const float* __restrict__ w1, const float* __restrict__ w2) {
    int idx = blockIdx.x * 256 + threadIdx.x;
    {
        int lane = idx & 31, ks = (idx >> 5) & 1, ng = (idx >> 6) & 15;
        int ch = (idx >> 10) & 7, tap = idx >> 13;
        int n = ng * 8 + (lane >> 2);
        int c0 = ch * 32 + ks * 16 + (lane & 3) * 2;
        float wa = w1[n * 2304 + c0 * 9 + tap];
        float wb = w1[n * 2304 + (c0 + 1) * 9 + tap];
        float wc = w1[n * 2304 + (c0 + 8) * 9 + tap];
        float wd = w1[n * 2304 + (c0 + 9) * 9 + tap];
        uint4 v;
        v.x = pack_hi(wa, wb);
        v.y = pack_hi(wc, wd);
        v.z = pack_lo(wa, wb);
        v.w = pack_lo(wc, wd);
        g_w1p[idx] = v;
    }
    if (idx < 256 * 128) {
        float w = w2[idx];
        __nv_bfloat16 h = __float2bfloat16(w);
        g_w2h[idx] = h;
        g_w2l[idx] = __float2bfloat16(w - __bfloat162float(h));
    }
}

// ---------------- conv1: staging distributed across taps ----------------
#define C1_ROWB  80
#define C1_PLB   (132 * C1_ROWB)
#define C1_HALF  (4 * C1_PLB)
#define C1_BUF   (2 * C1_HALF)
#define C1_SMEM  (2 * C1_BUF)                 // 168960
#define C1_TOT   (32 * 520)                   // staging elements per chunk = 16640
#define C1_SLICE 2080                         // per-tap slice (8 slices)

__global__ __launch_bounds__(512, 1) void conv1_tc(const float* __restrict__ x) {
    extern __shared__ char sm[];
    const uint32_t sb = smem_u32(sm);
    const int tid = threadIdx.x, lane = tid & 31, wid = tid >> 5;
    const int yb = blockIdx.x, b = blockIdx.y;
    const int y0 = yb * 2;
    const int m0w = (wid & 3) * 64;
    const int n0g = (wid >> 2) * 4;
    const int yw = m0w >> 7;
    const uint32_t aoff_lane = (uint32_t)((lane & 15) * C1_ROWB + (lane >> 4) * 16);

    float acc[4][4][4];
#pragma unroll
    for (int mi = 0; mi < 4; mi++)
#pragma unroll
        for (int j = 0; j < 4; j++)
#pragma unroll
            for (int q = 0; q < 4; q++) acc[mi][j][q] = 0.f;

    int ry[4];
#pragma unroll
    for (int pl = 0; pl < 4; pl++) {
        int r = y0 - 1 + pl;
        if (r < 0) r = 1;
        if (r > 127) r = 126;
        ry[pl] = r;
    }
    const float* xb = x + (size_t)b * Cn * HWn;

    // stage a range [lo, hi) of chunk ch's window into buffer buf
    auto stage_range = [&](int ch, int buf, int lo, int hi) {
        char* WH = sm + buf * C1_BUF;
        char* WL = WH + C1_HALF;
        for (int idx = lo + tid; idx < hi; idx += 512) {
            int cc = idx / 520, r = idx - cc * 520;
            int pl = r / 130, col = r - pl * 130;
            int cx = col - 1;
            if (cx < 0) cx = 1;
            if (cx > 127) cx = 126;
            float v = xb[(size_t)(ch * 32 + cc) * HWn + (size_t)ry[pl] * Wn + cx];
            __nv_bfloat16 h = __float2bfloat16(v);
            int off = pl * C1_PLB + col * C1_ROWB + cc * 2;
            *(__nv_bfloat16*)(WH + off) = h;
            *(__nv_bfloat16*)(WL + off) = __float2bfloat16(v - __bfloat162float(h));
        }
    };

    stage_range(0, 0, 0, C1_TOT);
    __syncthreads();

    for (int t = 0; t < 72; t++) {
        const int ch = t / 9, tap = t - ch * 9;
        const int ky = tap / 3, kx = tap - ky * 3;
        const int buf = ch & 1;
        const uint32_t WHb = sb + buf * C1_BUF;
        const uint32_t WLb = WHb + C1_HALF;
        const uint32_t pbase = (uint32_t)((ky + yw) * C1_PLB) +
                               (uint32_t)(((m0w & 127) + kx) * C1_ROWB) + aoff_lane;
        const uint4* wp = g_w1p + ((((size_t)tap * 8 + ch) * 16 + n0g) * 2) * 32 + lane;

        // distributed staging: taps 0..7 each stage 1/8 of chunk ch+1
        if (ch < 7 && tap < 8)
            stage_range(ch + 1, buf ^ 1, tap * C1_SLICE, (tap + 1) * C1_SLICE);

#pragma unroll
        for (int ks = 0; ks < 2; ks++) {
            uint4 B0 = wp[ks * 32];
            uint4 B1 = wp[ks * 32 + 64];
            uint4 B2 = wp[ks * 32 + 128];
            uint4 B3 = wp[ks * 32 + 192];
            const uint32_t kbyte = ks * 32;
#pragma unroll
            for (int mi = 0; mi < 4; mi++) {
                uint32_t ah[4], al[4];
                const uint32_t ao = pbase + (uint32_t)(mi * 16 * C1_ROWB) + kbyte;
                ldsm_x4(ah, WHb + ao);
                ldsm_x4(al, WLb + ao);
                mma_bf16(acc[mi][0], ah, B0.x, B0.y);
                mma_bf16(acc[mi][0], al, B0.x, B0.y);
                mma_bf16(acc[mi][0], ah, B0.z, B0.w);
                mma_bf16(acc[mi][1], ah, B1.x, B1.y);
                mma_bf16(acc[mi][1], al, B1.x, B1.y);
                mma_bf16(acc[mi][1], ah, B1.z, B1.w);
                mma_bf16(acc[mi][2], ah, B2.x, B2.y);
                mma_bf16(acc[mi][2], al, B2.x, B2.y);
                mma_bf16(acc[mi][2], ah, B2.z, B2.w);
                mma_bf16(acc[mi][3], ah, B3.x, B3.y);
                mma_bf16(acc[mi][3], al, B3.x, B3.y);
                mma_bf16(acc[mi][3], ah, B3.z, B3.w);
            }
        }
        if (tap == 8) __syncthreads();   // chunk boundary: staging of ch+1 complete+visible
    }

    const int dr = lane >> 2, dc = (lane & 3) * 2;
    const size_t slab = ((size_t)b * HWn + (size_t)y0 * Wn);
#pragma unroll
    for (int mi = 0; mi < 4; mi++)
#pragma unroll
        for (int j = 0; j < 4; j++) {
            int pix = m0w + mi * 16 + dr;
            int o = n0g * 8 + j * 8 + dc;
            float v0 = leaky(acc[mi][j][0]), v1 = leaky(acc[mi][j][1]);
            float v2 = leaky(acc[mi][j][2]), v3 = leaky(acc[mi][j][3]);
            size_t i1 = (slab + pix) * MIDn + o;
            size_t i2 = (slab + pix + 8) * MIDn + o;
            *(uint32_t*)(g_h1h + i1) = pack_hi(v0, v1);
            *(uint32_t*)(g_h1l + i1) = pack_lo(v0, v1);
            *(uint32_t*)(g_h1h + i2) = pack_hi(v2, v3);
            *(uint32_t*)(g_h1l + i2) = pack_lo(v2, v3);
        }
}

// ---------------- conv2: both kc stages resident, cp.async overlapped ----------------
#define GS_AH 0
#define GS_AL 36864
#define GS_BH 73728
#define GS_BL 92160
#define GS_SZ 110592
#define C2_PR (2 * GS_SZ)                     // 221184
#define C2_SMEM (C2_PR + 512)                 // 221696

__global__ __launch_bounds__(512, 1) void conv2_tc() {
    extern __shared__ char sm[];
    const uint32_t sb = smem_u32(sm);
    float* pr = (float*)(sm + C2_PR);
    const int tid = threadIdx.x, lane = tid & 31, wid = tid >> 5;
    const int yb = blockIdx.x, oh = blockIdx.y, b = blockIdx.z;
    const int m0w = (wid & 3) * 64, n0 = (wid >> 2) * 32;
    const uint32_t aoff = (uint32_t)((m0w + (lane & 15)) * ST + (lane >> 4) * 8) * 2;
    const uint32_t boff = (uint32_t)((n0 + (lane & 7) + ((lane >> 3) & 1) * 8) * ST + (lane >> 4) * 8) * 2;

    float acc[4][2][2][4];
#pragma unroll
    for (int mi = 0; mi < 4; mi++)
#pragma unroll
        for (int f = 0; f < 2; f++)
#pragma unroll
            for (int ns = 0; ns < 2; ns++)
#pragma unroll
                for (int q = 0; q < 4; q++) acc[mi][f][ns][q] = 0.f;

    const size_t slab = (size_t)b * HWn + (size_t)yb * 256;

    auto issueStage = [&](int s) {
        const uint32_t base = sb + s * GS_SZ;
        const int kc = s * 64;
        for (int i = tid; i < 2048; i += 512) {
            int row = i >> 3, q = i & 7;
            uint32_t so = (uint32_t)(row * ST + q * 8) * 2;
            cp16(base + GS_AH + so, g_h1h + (slab + row) * MIDn + kc + q * 8);
            cp16(base + GS_AL + so, g_h1l + (slab + row) * MIDn + kc + q * 8);
            if (i < 1024) {
                cp16(base + GS_BH + so, g_w2h + (size_t)(oh * 128 + row) * MIDn + kc + q * 8);
                cp16(base + GS_BL + so, g_w2l + (size_t)(oh * 128 + row) * MIDn + kc + q * 8);
            }
        }
        CP_COMMIT();
    };
    auto computeStage = [&](int s) {
        const uint32_t base = sb + s * GS_SZ;
#pragma unroll
        for (int ks = 0; ks < 4; ks++) {
            const uint32_t kb = ks * 32;
            uint32_t bhm[8], blm[8];
            ldsm_x4(bhm,     base + GS_BH + boff + kb);
            ldsm_x4(bhm + 4, base + GS_BH + boff + 16 * ST * 2 + kb);
            ldsm_x4(blm,     base + GS_BL + boff + kb);
            ldsm_x4(blm + 4, base + GS_BL + boff + 16 * ST * 2 + kb);
#pragma unroll
            for (int mi = 0; mi < 4; mi++) {
                uint32_t ah[4], al[4];
                ldsm_x4(ah, base + GS_AH + aoff + mi * 16 * ST * 2 + kb);
                ldsm_x4(al, base + GS_AL + aoff + mi * 16 * ST * 2 + kb);
#pragma unroll
                for (int f = 0; f < 2; f++) {
                    mma_bf16(acc[mi][f][0], ah, bhm[4 * f],     bhm[4 * f + 2]);
                    mma_bf16(acc[mi][f][0], ah, blm[4 * f],     blm[4 * f + 2]);
                    mma_bf16(acc[mi][f][0], al, bhm[4 * f],     bhm[4 * f + 2]);
                    mma_bf16(acc[mi][f][1], ah, bhm[4 * f + 1], bhm[4 * f + 3]);
                    mma_bf16(acc[mi][f][1], ah, blm[4 * f + 1], blm[4 * f + 3]);
                    mma_bf16(acc[mi][f][1], al, bhm[4 * f + 1], bhm[4 * f + 3]);
                }
            }
        }
    };

    issueStage(0);
    issueStage(1);
    CP_WAIT1();
    __syncthreads();
    computeStage(0);
    CP_WAIT0();
    __syncthreads();
    computeStage(1);

    __syncthreads();
    if (tid < 128) pr[tid] = 0.f;
    __syncthreads();
    const int dr = lane >> 2, dc = (lane & 3) * 2;
#pragma unroll
    for (int f = 0; f < 2; f++)
#pragma unroll
        for (int ns = 0; ns < 2; ns++) {
            int cl = n0 + f * 16 + ns * 8 + dc;
            float s0 = 0.f, s1 = 0.f;
#pragma unroll
            for (int mi = 0; mi < 4; mi++) {
                int pix = m0w + mi * 16 + dr;
                float v0 = leaky(acc[mi][f][ns][0]), v1 = leaky(acc[mi][f][ns][1]);
                float v2 = leaky(acc[mi][f][ns][2]), v3 = leaky(acc[mi][f][ns][3]);
                size_t i1 = (slab + pix) * Cn + oh * 128 + cl;
                size_t i2 = (slab + pix + 8) * Cn + oh * 128 + cl;
                *(uint32_t*)(g_xch + i1) = pack_hi(v0, v1);
                *(uint32_t*)(g_xcl + i1) = pack_lo(v0, v1);
                *(uint32_t*)(g_xch + i2) = pack_hi(v2, v3);
                *(uint32_t*)(g_xcl + i2) = pack_lo(v2, v3);
                s0 += v0 + v2;
                s1 += v1 + v3;
            }
            atomicAdd(&pr[cl], s0);
            atomicAdd(&pr[cl + 1], s1);
        }
    __syncthreads();
    if (tid < 128)
        g_ppart[(((size_t)b * 64 + yb) * 2 + oh) * 128 + tid] = pr[tid];
}

// ---------------- pool2 ----------------
__global__ void pool2_kernel() {
    const int b = blockIdx.x, tid = threadIdx.x;
    const int oh = tid >> 7, cl = tid & 127;
    float s = 0.f;
    for (int yb = 0; yb < 64; yb++)
        s += g_ppart[(((size_t)b * 64 + yb) * 2 + oh) * 128 + cl];
    g_pooled[b * Cn + tid] = s * (1.0f / (float)HWn);
}

// ---------------- MLP + outer score + softmax ----------------
__global__ void mlp_score_kernel(const float* __restrict__ w1, const float* __restrict__ b1,
                                 const float* __restrict__ w2, const float* __restrict__ b2) {
    const int b = blockIdx.x, tid = threadIdx.x;
    __shared__ float sp[256], sh[64], sm_[256];
    sp[tid] = g_pooled[b * 256 + tid];
    __syncthreads();
    if (tid < 64) {
        float s = b1[tid];
        for (int c = 0; c < 256; c++) s += sp[c] * w1[tid * 256 + c];
        sh[tid] = leaky(s);
    }
    __syncthreads();
    {
        float s = b2[tid];
        for (int j = 0; j < 64; j++) s += sh[j] * w2[tid * 64 + j];
        sm_[tid] = s;
    }
    __syncthreads();
    const int lane = tid & 31, w = tid >> 5;
    for (int r = w; r < 256; r += 8) {
        float mr = sm_[r];
        float mx = -1e30f;
        for (int e = lane; e < 256; e += 32) mx = fmaxf(mx, mr * sm_[e]);
        for (int off = 16; off; off >>= 1) mx = fmaxf(mx, __shfl_xor_sync(~0u, mx, off));
        float sum = 0.f;
        for (int e = lane; e < 256; e += 32) sum += expf(mr * sm_[e] - mx);
        for (int off = 16; off; off >>= 1) sum += __shfl_xor_sync(~0u, sum, off);
        float inv = 1.0f / sum;
        for (int e = lane; e < 256; e += 32) {
            float s = expf(mr * sm_[e] - mx) * inv;
            __nv_bfloat16 h = __float2bfloat16(s);
            size_t off2 = ((size_t)b * 256 + r) * 256 + e;
            g_scoreH[off2] = h;
            g_scoreL[off2] = __float2bfloat16(s - __bfloat162float(h));
        }
    }
}

// ---------------- attn: 4 kc stages, 2-deep cp.async pipeline ----------------
#define AT_SMEM (2 * GS_SZ)                   // 221184

__global__ __launch_bounds__(512, 1) void attn_tc(float* __restrict__ out) {
    extern __shared__ char sm[];
    const uint32_t sb = smem_u32(sm);
    const int tid = threadIdx.x, lane = tid & 31, wid = tid >> 5;
    const int yb = blockIdx.x, mh = blockIdx.y, b = blockIdx.z;
    const int m0w = (wid & 3) * 64, n0 = (wid >> 2) * 32;
    const int yw = m0w >> 7;
    const uint32_t aoff = (uint32_t)((m0w + (lane & 15)) * ST + (lane >> 4) * 8) * 2;
    const uint32_t boff = (uint32_t)((n0 + (lane & 7) + ((lane >> 3) & 1) * 8) * ST + (lane >> 4) * 8) * 2;

    float acc[4][2][2][4];
#pragma unroll
    for (int mi = 0; mi < 4; mi++)
#pragma unroll
        for (int f = 0; f < 2; f++)
#pragma unroll
            for (int ns = 0; ns < 2; ns++)
#pragma unroll
                for (int q = 0; q < 4; q++) acc[mi][f][ns][q] = 0.f;

    const size_t slab = (size_t)b * HWn + (size_t)yb * 256;

    auto issueStage = [&](int s) {
        const uint32_t base = sb + (s & 1) * GS_SZ;
        const int kc = s * 64;
        for (int i = tid; i < 2048; i += 512) {
            int row = i >> 3, q = i & 7;
            uint32_t so = (uint32_t)(row * ST + q * 8) * 2;
            cp16(base + GS_AH + so, g_xch + (slab + row) * Cn + kc + q * 8);
            cp16(base + GS_AL + so, g_xcl + (slab + row) * Cn + kc + q * 8);
            if (i < 1024) {
                cp16(base + GS_BH + so, g_scoreH + ((size_t)b * 256 + mh * 128 + row) * 256 + kc + q * 8);
                cp16(base + GS_BL + so, g_scoreL + ((size_t)b * 256 + mh * 128 + row) * 256 + kc + q * 8);
            }
        }
        CP_COMMIT();
    };
    auto computeStage = [&](int s) {
        const uint32_t base = sb + (s & 1) * GS_SZ;
#pragma unroll
        for (int ks = 0; ks < 4; ks++) {
            const uint32_t kb = ks * 32;
            uint32_t bhm[8], blm[8];
            ldsm_x4(bhm,     base + GS_BH + boff + kb);
            ldsm_x4(bhm + 4, base + GS_BH + boff + 16 * ST * 2 + kb);
            ldsm_x4(blm,     base + GS_BL + boff + kb);
            ldsm_x4(blm + 4, base + GS_BL + boff + 16 * ST * 2 + kb);
#pragma unroll
            for (int mi = 0; mi < 4; mi++) {
                uint32_t ah[4], al[4];
                ldsm_x4(ah, base + GS_AH + aoff + mi * 16 * ST * 2 + kb);
                ldsm_x4(al, base + GS_AL + aoff + mi * 16 * ST * 2 + kb);
#pragma unroll
                for (int f = 0; f < 2; f++) {
                    mma_bf16(acc[mi][f][0], ah, bhm[4 * f],     bhm[4 * f + 2]);
                    mma_bf16(acc[mi][f][0], ah, blm[4 * f],     blm[4 * f + 2]);
                    mma_bf16(acc[mi][f][0], al, bhm[4 * f],     bhm[4 * f + 2]);
                    mma_bf16(acc[mi][f][1], ah, bhm[4 * f + 1], bhm[4 * f + 3]);
                    mma_bf16(acc[mi][f][1], ah, blm[4 * f + 1], blm[4 * f + 3]);
                    mma_bf16(acc[mi][f][1], al, bhm[4 * f + 1], bhm[4 * f + 3]);
                }
            }
        }
    };

    issueStage(0);
    for (int s = 0; s < 4; s++) {
        if (s + 1 < 4) {
            issueStage(s + 1);
            CP_WAIT1();
        } else {
            CP_WAIT0();
        }
        __syncthreads();
        computeStage(s);
        __syncthreads();
    }

    float* sT = (float*)sm;
    const int dr = lane >> 2, dc = (lane & 3) * 2;
    for (int yw2 = 0; yw2 < 2; yw2++) {
        if (yw == yw2) {
#pragma unroll
            for (int mi = 0; mi < 4; mi++)
#pragma unroll
                for (int f = 0; f < 2; f++)
#pragma unroll
                    for (int ns = 0; ns < 2; ns++) {
                        int pix = m0w + mi * 16 + dr;
                        int c = n0 + f * 16 + ns * 8 + dc;
                        size_t i1 = (slab + pix) * Cn + mh * 128 + c;
                        size_t i2 = (slab + pix + 8) * Cn + mh * 128 + c;
                        float r0 = __bfloat162float(g_xch[i1])     + __bfloat162float(g_xcl[i1]);
                        float r1 = __bfloat162float(g_xch[i1 + 1]) + __bfloat162float(g_xcl[i1 + 1]);
                        float r2 = __bfloat162float(g_xch[i2])     + __bfloat162float(g_xcl[i2]);
                        float r3 = __bfloat162float(g_xch[i2 + 1]) + __bfloat162float(g_xcl[i2 + 1]);
                        int p = pix & 127;
                        sT[c * 132 + p]           = acc[mi][f][ns][0] + r0;
                        sT[(c + 1) * 132 + p]     = acc[mi][f][ns][1] + r1;
                        sT[c * 132 + p + 8]       = acc[mi][f][ns][2] + r2;
                        sT[(c + 1) * 132 + p + 8] = acc[mi][f][ns][3] + r3;
                    }
        }
        __syncthreads();
        for (int i = tid; i < 16384; i += 512) {
            int c = i >> 7, p = i & 127;
            out[(((size_t)b * 256 + mh * 128 + c) * Hn + yb * 2 + yw2) * Wn + p] = sT[c * 132 + p];
        }
        __syncthreads();
    }
}

// ---------------- launcher ----------------
extern "C" void kernel_launch(void* const* d_in, const int* in_sizes, int n_in,
                              void* d_out, int out_size) {
    const float* x   = (const float*)d_in[0];
    const float* c1w = (const float*)d_in[1];
    const float* c2w = (const float*)d_in[2];
    const float* mw1 = (const float*)d_in[3];
    const float* mb1 = (const float*)d_in[4];
    const float* mw2 = (const float*)d_in[5];
    const float* mb2 = (const float*)d_in[6];
    float* out = (float*)d_out;

    cudaFuncSetAttribute(conv1_tc, cudaFuncAttributeMaxDynamicSharedMemorySize, C1_SMEM);
    cudaFuncSetAttribute(conv2_tc, cudaFuncAttributeMaxDynamicSharedMemorySize, C2_SMEM);
    cudaFuncSetAttribute(attn_tc,  cudaFuncAttributeMaxDynamicSharedMemorySize, AT_SMEM);

    dummy_kernel<<<1, 32>>>();
    dummy_kernel<<<1, 32>>>();
    prep_kernel<<<288, 256>>>(c1w, c2w);
    conv1_tc<<<dim3(64, Bn), 512, C1_SMEM>>>(x);
    conv2_tc<<<dim3(64, 2, Bn), 512, C2_SMEM>>>();
    pool2_kernel<<<Bn, 256>>>();
    mlp_score_kernel<<<Bn, 256>>>(mw1, mb1, mw2, mb2);
    attn_tc<<<dim3(64, 2, Bn), 512, AT_SMEM>>>(out);
}

// round 17
// speedup vs baseline: 1.1631x; 1.1631x over previous
#include <cuda_runtime.h>
#include <cuda_bf16.h>
#include <cstdint>
#include <math.h>

#define Bn   16
#define Cn   256
#define MIDn 128
#define Hn   128
#define Wn   128
#define HWn  (Hn*Wn)
#define ST   72

// ================= warp-MMA helpers =================
__device__ __forceinline__ uint32_t smem_u32(const void* p) {
    uint32_t a;
    asm("{ .reg .u64 t; cvta.to.shared.u64 t, %1; cvt.u32.u64 %0, t; }" : "=r"(a) : "l"(p));
    return a;
}
__device__ __forceinline__ void ldsm_x4(uint32_t* r, uint32_t addr) {
    asm volatile("ldmatrix.sync.aligned.m8n8.x4.shared.b16 {%0,%1,%2,%3}, [%4];"
                 : "=r"(r[0]), "=r"(r[1]), "=r"(r[2]), "=r"(r[3]) : "r"(addr));
}
__device__ __forceinline__ void mma_bf16(float* d, const uint32_t* a, uint32_t b0, uint32_t b1) {
    asm volatile("mma.sync.aligned.m16n8k16.row.col.f32.bf16.bf16.f32 "
                 "{%0,%1,%2,%3}, {%4,%5,%6,%7}, {%8,%9}, {%0,%1,%2,%3};"
                 : "+f"(d[0]), "+f"(d[1]), "+f"(d[2]), "+f"(d[3])
                 : "r"(a[0]), "r"(a[1]), "r"(a[2]), "r"(a[3]), "r"(b0), "r"(b1));
}
__device__ __forceinline__ void cp16(uint32_t saddr, const void* g) {
    asm volatile("cp.async.cg.shared.global [%0], [%1], 16;" :: "r"(saddr), "l"(g) : "memory");
}
#define CP_COMMIT() asm volatile("cp.async.commit_group;" ::: "memory")
#define CP_WAIT0()  asm volatile("cp.async.wait_group 0;" ::: "memory")
#define CP_WAIT1()  asm volatile("cp.async.wait_group 1;" ::: "memory")
__device__ __forceinline__ float leaky(float v) { return v >= 0.f ? v : 0.2f * v; }
__device__ __forceinline__ uint32_t pack_hi(float a, float b) {
    __nv_bfloat16 h0 = __float2bfloat16(a), h1 = __float2bfloat16(b);
    return (uint32_t)__bfloat16_as_ushort(h0) | ((uint32_t)__bfloat16_as_ushort(h1) << 16);
}
__device__ __forceinline__ uint32_t pack_lo(float a, float b) {
    __nv_bfloat16 h0 = __float2bfloat16(a), h1 = __float2bfloat16(b);
    __nv_bfloat16 l0 = __float2bfloat16(a - __bfloat162float(h0));
    __nv_bfloat16 l1 = __float2bfloat16(b - __bfloat162float(h1));
    return (uint32_t)__bfloat16_as_ushort(l0) | ((uint32_t)__bfloat16_as_ushort(l1) << 16);
}

// ================= scratch =================
__device__ uint4 g_w1p[9 * 8 * 16 * 2 * 32];        // conv1 B-fragments
__device__ __nv_bfloat16 g_w2h[256 * 128];
__device__ __nv_bfloat16 g_w2l[256 * 128];
__device__ __nv_bfloat16 g_h1h[(size_t)Bn * HWn * MIDn];
__device__ __nv_bfloat16 g_h1l[(size_t)Bn * HWn * MIDn];
__device__ __nv_bfloat16 g_xch[(size_t)Bn * HWn * Cn];
__device__ __nv_bfloat16 g_xcl[(size_t)Bn * HWn * Cn];
__device__ float g_ppart[Bn * 64 * 2 * 128];
__device__ float g_pooled[Bn * Cn];
__device__ __nv_bfloat16 g_scoreH[(size_t)Bn * Cn * Cn];
__device__ __nv_bfloat16 g_scoreL[(size_t)Bn * Cn * Cn];

// ---------------- dummy (keeps ncu's sampled launch index on conv1) ----------------
__global__ void dummy_kernel() {}

// ---------------- kernel 0: weight prep ----------------
__global__ void prep_kernel(const float* __restrict__ w1, const float* __restrict__ w2) {
    int idx = blockIdx.x * 256 + threadIdx.x;
    {
        int lane = idx & 31, ks = (idx >> 5) & 1, ng = (idx >> 6) & 15;
        int ch = (idx >> 10) & 7, tap = idx >> 13;
        int n = ng * 8 + (lane >> 2);
        int c0 = ch * 32 + ks * 16 + (lane & 3) * 2;
        float wa = w1[n * 2304 + c0 * 9 + tap];
        float wb = w1[n * 2304 + (c0 + 1) * 9 + tap];
        float wc = w1[n * 2304 + (c0 + 8) * 9 + tap];
        float wd = w1[n * 2304 + (c0 + 9) * 9 + tap];
        uint4 v;
        v.x = pack_hi(wa, wb);
        v.y = pack_hi(wc, wd);
        v.z = pack_lo(wa, wb);
        v.w = pack_lo(wc, wd);
        g_w1p[idx] = v;
    }
    if (idx < 256 * 128) {
        float w = w2[idx];
        __nv_bfloat16 h = __float2bfloat16(w);
        g_w2h[idx] = h;
        g_w2l[idx] = __float2bfloat16(w - __bfloat162float(h));
    }
}

// ---------------- conv1: staggered per-warp staging ----------------
#define C1_ROWB  80
#define C1_PLB   (132 * C1_ROWB)
#define C1_HALF  (4 * C1_PLB)
#define C1_BUF   (2 * C1_HALF)
#define C1_SMEM  (2 * C1_BUF)                 // 168960
#define C1_TOT   (32 * 520)                   // staging elements per chunk = 16640
#define C1_WSL   1040                         // per-warp slice (16 slices)

__global__ __launch_bounds__(512, 1) void conv1_tc(const float* __restrict__ x) {
    extern __shared__ char sm[];
    const uint32_t sb = smem_u32(sm);
    const int tid = threadIdx.x, lane = tid & 31, wid = tid >> 5;
    const int yb = blockIdx.x, b = blockIdx.y;
    const int y0 = yb * 2;
    const int m0w = (wid & 3) * 64;
    const int n0g = (wid >> 2) * 4;
    const int yw = m0w >> 7;
    const uint32_t aoff_lane = (uint32_t)((lane & 15) * C1_ROWB + (lane >> 4) * 16);

    float acc[4][4][4];
#pragma unroll
    for (int mi = 0; mi < 4; mi++)
#pragma unroll
        for (int j = 0; j < 4; j++)
#pragma unroll
            for (int q = 0; q < 4; q++) acc[mi][j][q] = 0.f;

    int ry[4];
#pragma unroll
    for (int pl = 0; pl < 4; pl++) {
        int r = y0 - 1 + pl;
        if (r < 0) r = 1;
        if (r > 127) r = 126;
        ry[pl] = r;
    }
    const float* xb = x + (size_t)b * Cn * HWn;

    // stage elements [lo, hi) of chunk ch's window into buffer buf, using `step` threads
    auto stage_range = [&](int ch, int buf, int lo, int hi, int tbase, int step) {
        char* WH = sm + buf * C1_BUF;
        char* WL = WH + C1_HALF;
        for (int idx = lo + tbase; idx < hi; idx += step) {
            int cc = idx / 520, r = idx - cc * 520;
            int pl = r / 130, col = r - pl * 130;
            int cx = col - 1;
            if (cx < 0) cx = 1;
            if (cx > 127) cx = 126;
            float v = xb[(size_t)(ch * 32 + cc) * HWn + (size_t)ry[pl] * Wn + cx];
            __nv_bfloat16 h = __float2bfloat16(v);
            int off = pl * C1_PLB + col * C1_ROWB + cc * 2;
            *(__nv_bfloat16*)(WH + off) = h;
            *(__nv_bfloat16*)(WL + off) = __float2bfloat16(v - __bfloat162float(h));
        }
    };

    stage_range(0, 0, 0, C1_TOT, tid, 512);
    __syncthreads();

    for (int t = 0; t < 72; t++) {
        const int ch = t / 9, tap = t - ch * 9;
        const int ky = tap / 3, kx = tap - ky * 3;
        const int buf = ch & 1;
        const uint32_t WHb = sb + buf * C1_BUF;
        const uint32_t WLb = WHb + C1_HALF;
        const uint32_t pbase = (uint32_t)((ky + yw) * C1_PLB) +
                               (uint32_t)(((m0w & 127) + kx) * C1_ROWB) + aoff_lane;
        const uint4* wp = g_w1p + ((((size_t)tap * 8 + ch) * 16 + n0g) * 2) * 32 + lane;

        // staggered staging: warp w stages its private 1/16 slice of chunk ch+1
        // at tap (w & 7).  Only 2 of 16 warps stage per tap; each warp stalls
        // once per chunk.  tap==8 barrier (below) makes all slices visible.
        if (ch < 7 && tap == (wid & 7))
            stage_range(ch + 1, buf ^ 1, wid * C1_WSL, (wid + 1) * C1_WSL, lane, 32);

#pragma unroll
        for (int ks = 0; ks < 2; ks++) {
            uint4 B0 = wp[ks * 32];
            uint4 B1 = wp[ks * 32 + 64];
            uint4 B2 = wp[ks * 32 + 128];
            uint4 B3 = wp[ks * 32 + 192];
            const uint32_t kbyte = ks * 32;
#pragma unroll
            for (int mi = 0; mi < 4; mi++) {
                uint32_t ah[4], al[4];
                const uint32_t ao = pbase + (uint32_t)(mi * 16 * C1_ROWB) + kbyte;
                ldsm_x4(ah, WHb + ao);
                ldsm_x4(al, WLb + ao);
                mma_bf16(acc[mi][0], ah, B0.x, B0.y);
                mma_bf16(acc[mi][0], al, B0.x, B0.y);
                mma_bf16(acc[mi][0], ah, B0.z, B0.w);
                mma_bf16(acc[mi][1], ah, B1.x, B1.y);
                mma_bf16(acc[mi][1], al, B1.x, B1.y);
                mma_bf16(acc[mi][1], ah, B1.z, B1.w);
                mma_bf16(acc[mi][2], ah, B2.x, B2.y);
                mma_bf16(acc[mi][2], al, B2.x, B2.y);
                mma_bf16(acc[mi][2], ah, B2.z, B2.w);
                mma_bf16(acc[mi][3], ah, B3.x, B3.y);
                mma_bf16(acc[mi][3], al, B3.x, B3.y);
                mma_bf16(acc[mi][3], ah, B3.z, B3.w);
            }
        }
        if (tap == 8) __syncthreads();   // chunk boundary: staging complete + visible
    }

    const int dr = lane >> 2, dc = (lane & 3) * 2;
    const size_t slab = ((size_t)b * HWn + (size_t)y0 * Wn);
#pragma unroll
    for (int mi = 0; mi < 4; mi++)
#pragma unroll
        for (int j = 0; j < 4; j++) {
            int pix = m0w + mi * 16 + dr;
            int o = n0g * 8 + j * 8 + dc;
            float v0 = leaky(acc[mi][j][0]), v1 = leaky(acc[mi][j][1]);
            float v2 = leaky(acc[mi][j][2]), v3 = leaky(acc[mi][j][3]);
            size_t i1 = (slab + pix) * MIDn + o;
            size_t i2 = (slab + pix + 8) * MIDn + o;
            *(uint32_t*)(g_h1h + i1) = pack_hi(v0, v1);
            *(uint32_t*)(g_h1l + i1) = pack_lo(v0, v1);
            *(uint32_t*)(g_h1h + i2) = pack_hi(v2, v3);
            *(uint32_t*)(g_h1l + i2) = pack_lo(v2, v3);
        }
}

// ---------------- conv2: both kc stages resident, cp.async overlapped ----------------
#define GS_AH 0
#define GS_AL 36864
#define GS_BH 73728
#define GS_BL 92160
#define GS_SZ 110592
#define C2_PR (2 * GS_SZ)                     // 221184
#define C2_SMEM (C2_PR + 512)                 // 221696

__global__ __launch_bounds__(512, 1) void conv2_tc() {
    extern __shared__ char sm[];
    const uint32_t sb = smem_u32(sm);
    float* pr = (float*)(sm + C2_PR);
    const int tid = threadIdx.x, lane = tid & 31, wid = tid >> 5;
    const int yb = blockIdx.x, oh = blockIdx.y, b = blockIdx.z;
    const int m0w = (wid & 3) * 64, n0 = (wid >> 2) * 32;
    const uint32_t aoff = (uint32_t)((m0w + (lane & 15)) * ST + (lane >> 4) * 8) * 2;
    const uint32_t boff = (uint32_t)((n0 + (lane & 7) + ((lane >> 3) & 1) * 8) * ST + (lane >> 4) * 8) * 2;

    float acc[4][2][2][4];
#pragma unroll
    for (int mi = 0; mi < 4; mi++)
#pragma unroll
        for (int f = 0; f < 2; f++)
#pragma unroll
            for (int ns = 0; ns < 2; ns++)
#pragma unroll
                for (int q = 0; q < 4; q++) acc[mi][f][ns][q] = 0.f;

    const size_t slab = (size_t)b * HWn + (size_t)yb * 256;

    auto issueStage = [&](int s) {
        const uint32_t base = sb + s * GS_SZ;
        const int kc = s * 64;
        for (int i = tid; i < 2048; i += 512) {
            int row = i >> 3, q = i & 7;
            uint32_t so = (uint32_t)(row * ST + q * 8) * 2;
            cp16(base + GS_AH + so, g_h1h + (slab + row) * MIDn + kc + q * 8);
            cp16(base + GS_AL + so, g_h1l + (slab + row) * MIDn + kc + q * 8);
            if (i < 1024) {
                cp16(base + GS_BH + so, g_w2h + (size_t)(oh * 128 + row) * MIDn + kc + q * 8);
                cp16(base + GS_BL + so, g_w2l + (size_t)(oh * 128 + row) * MIDn + kc + q * 8);
            }
        }
        CP_COMMIT();
    };
    auto computeStage = [&](int s) {
        const uint32_t base = sb + s * GS_SZ;
#pragma unroll
        for (int ks = 0; ks < 4; ks++) {
            const uint32_t kb = ks * 32;
            uint32_t bhm[8], blm[8];
            ldsm_x4(bhm,     base + GS_BH + boff + kb);
            ldsm_x4(bhm + 4, base + GS_BH + boff + 16 * ST * 2 + kb);
            ldsm_x4(blm,     base + GS_BL + boff + kb);
            ldsm_x4(blm + 4, base + GS_BL + boff + 16 * ST * 2 + kb);
#pragma unroll
            for (int mi = 0; mi < 4; mi++) {
                uint32_t ah[4], al[4];
                ldsm_x4(ah, base + GS_AH + aoff + mi * 16 * ST * 2 + kb);
                ldsm_x4(al, base + GS_AL + aoff + mi * 16 * ST * 2 + kb);
#pragma unroll
                for (int f = 0; f < 2; f++) {
                    mma_bf16(acc[mi][f][0], ah, bhm[4 * f],     bhm[4 * f + 2]);
                    mma_bf16(acc[mi][f][0], ah, blm[4 * f],     blm[4 * f + 2]);
                    mma_bf16(acc[mi][f][0], al, bhm[4 * f],     bhm[4 * f + 2]);
                    mma_bf16(acc[mi][f][1], ah, bhm[4 * f + 1], bhm[4 * f + 3]);
                    mma_bf16(acc[mi][f][1], ah, blm[4 * f + 1], blm[4 * f + 3]);
                    mma_bf16(acc[mi][f][1], al, bhm[4 * f + 1], bhm[4 * f + 3]);
                }
            }
        }
    };

    issueStage(0);
    issueStage(1);
    CP_WAIT1();
    __syncthreads();
    computeStage(0);
    CP_WAIT0();
    __syncthreads();
    computeStage(1);

    __syncthreads();
    if (tid < 128) pr[tid] = 0.f;
    __syncthreads();
    const int dr = lane >> 2, dc = (lane & 3) * 2;
#pragma unroll
    for (int f = 0; f < 2; f++)
#pragma unroll
        for (int ns = 0; ns < 2; ns++) {
            int cl = n0 + f * 16 + ns * 8 + dc;
            float s0 = 0.f, s1 = 0.f;
#pragma unroll
            for (int mi = 0; mi < 4; mi++) {
                int pix = m0w + mi * 16 + dr;
                float v0 = leaky(acc[mi][f][ns][0]), v1 = leaky(acc[mi][f][ns][1]);
                float v2 = leaky(acc[mi][f][ns][2]), v3 = leaky(acc[mi][f][ns][3]);
                size_t i1 = (slab + pix) * Cn + oh * 128 + cl;
                size_t i2 = (slab + pix + 8) * Cn + oh * 128 + cl;
                *(uint32_t*)(g_xch + i1) = pack_hi(v0, v1);
                *(uint32_t*)(g_xcl + i1) = pack_lo(v0, v1);
                *(uint32_t*)(g_xch + i2) = pack_hi(v2, v3);
                *(uint32_t*)(g_xcl + i2) = pack_lo(v2, v3);
                s0 += v0 + v2;
                s1 += v1 + v3;
            }
            atomicAdd(&pr[cl], s0);
            atomicAdd(&pr[cl + 1], s1);
        }
    __syncthreads();
    if (tid < 128)
        g_ppart[(((size_t)b * 64 + yb) * 2 + oh) * 128 + tid] = pr[tid];
}

// ---------------- pool2 ----------------
__global__ void pool2_kernel() {
    const int b = blockIdx.x, tid = threadIdx.x;
    const int oh = tid >> 7, cl = tid & 127;
    float s = 0.f;
    for (int yb = 0; yb < 64; yb++)
        s += g_ppart[(((size_t)b * 64 + yb) * 2 + oh) * 128 + cl];
    g_pooled[b * Cn + tid] = s * (1.0f / (float)HWn);
}

// ---------------- MLP + outer score + softmax ----------------
__global__ void mlp_score_kernel(const float* __restrict__ w1, const float* __restrict__ b1,
                                 const float* __restrict__ w2, const float* __restrict__ b2) {
    const int b = blockIdx.x, tid = threadIdx.x;
    __shared__ float sp[256], sh[64], sm_[256];
    sp[tid] = g_pooled[b * 256 + tid];
    __syncthreads();
    if (tid < 64) {
        float s = b1[tid];
        for (int c = 0; c < 256; c++) s += sp[c] * w1[tid * 256 + c];
        sh[tid] = leaky(s);
    }
    __syncthreads();
    {
        float s = b2[tid];
        for (int j = 0; j < 64; j++) s += sh[j] * w2[tid * 64 + j];
        sm_[tid] = s;
    }
    __syncthreads();
    const int lane = tid & 31, w = tid >> 5;
    for (int r = w; r < 256; r += 8) {
        float mr = sm_[r];
        float mx = -1e30f;
        for (int e = lane; e < 256; e += 32) mx = fmaxf(mx, mr * sm_[e]);
        for (int off = 16; off; off >>= 1) mx = fmaxf(mx, __shfl_xor_sync(~0u, mx, off));
        float sum = 0.f;
        for (int e = lane; e < 256; e += 32) sum += expf(mr * sm_[e] - mx);
        for (int off = 16; off; off >>= 1) sum += __shfl_xor_sync(~0u, sum, off);
        float inv = 1.0f / sum;
        for (int e = lane; e < 256; e += 32) {
            float s = expf(mr * sm_[e] - mx) * inv;
            __nv_bfloat16 h = __float2bfloat16(s);
            size_t off2 = ((size_t)b * 256 + r) * 256 + e;
            g_scoreH[off2] = h;
            g_scoreL[off2] = __float2bfloat16(s - __bfloat162float(h));
        }
    }
}

// ---------------- attn: 4 kc stages, 2-deep cp.async pipeline ----------------
#define AT_SMEM (2 * GS_SZ)                   // 221184

__global__ __launch_bounds__(512, 1) void attn_tc(float* __restrict__ out) {
    extern __shared__ char sm[];
    const uint32_t sb = smem_u32(sm);
    const int tid = threadIdx.x, lane = tid & 31, wid = tid >> 5;
    const int yb = blockIdx.x, mh = blockIdx.y, b = blockIdx.z;
    const int m0w = (wid & 3) * 64, n0 = (wid >> 2) * 32;
    const int yw = m0w >> 7;
    const uint32_t aoff = (uint32_t)((m0w + (lane & 15)) * ST + (lane >> 4) * 8) * 2;
    const uint32_t boff = (uint32_t)((n0 + (lane & 7) + ((lane >> 3) & 1) * 8) * ST + (lane >> 4) * 8) * 2;

    float acc[4][2][2][4];
#pragma unroll
    for (int mi = 0; mi < 4; mi++)
#pragma unroll
        for (int f = 0; f < 2; f++)
#pragma unroll
            for (int ns = 0; ns < 2; ns++)
#pragma unroll
                for (int q = 0; q < 4; q++) acc[mi][f][ns][q] = 0.f;

    const size_t slab = (size_t)b * HWn + (size_t)yb * 256;

    auto issueStage = [&](int s) {
        const uint32_t base = sb + (s & 1) * GS_SZ;
        const int kc = s * 64;
        for (int i = tid; i < 2048; i += 512) {
            int row = i >> 3, q = i & 7;
            uint32_t so = (uint32_t)(row * ST + q * 8) * 2;
            cp16(base + GS_AH + so, g_xch + (slab + row) * Cn + kc + q * 8);
            cp16(base + GS_AL + so, g_xcl + (slab + row) * Cn + kc + q * 8);
            if (i < 1024) {
                cp16(base + GS_BH + so, g_scoreH + ((size_t)b * 256 + mh * 128 + row) * 256 + kc + q * 8);
                cp16(base + GS_BL + so, g_scoreL + ((size_t)b * 256 + mh * 128 + row) * 256 + kc + q * 8);
            }
        }
        CP_COMMIT();
    };
    auto computeStage = [&](int s) {
        const uint32_t base = sb + (s & 1) * GS_SZ;
#pragma unroll
        for (int ks = 0; ks < 4; ks++) {
            const uint32_t kb = ks * 32;
            uint32_t bhm[8], blm[8];
            ldsm_x4(bhm,     base + GS_BH + boff + kb);
            ldsm_x4(bhm + 4, base + GS_BH + boff + 16 * ST * 2 + kb);
            ldsm_x4(blm,     base + GS_BL + boff + kb);
            ldsm_x4(blm + 4, base + GS_BL + boff + 16 * ST * 2 + kb);
#pragma unroll
            for (int mi = 0; mi < 4; mi++) {
                uint32_t ah[4], al[4];
                ldsm_x4(ah, base + GS_AH + aoff + mi * 16 * ST * 2 + kb);
                ldsm_x4(al, base + GS_AL + aoff + mi * 16 * ST * 2 + kb);
#pragma unroll
                for (int f = 0; f < 2; f++) {
                    mma_bf16(acc[mi][f][0], ah, bhm[4 * f],     bhm[4 * f + 2]);
                    mma_bf16(acc[mi][f][0], ah, blm[4 * f],     blm[4 * f + 2]);
                    mma_bf16(acc[mi][f][0], al, bhm[4 * f],     bhm[4 * f + 2]);
                    mma_bf16(acc[mi][f][1], ah, bhm[4 * f + 1], bhm[4 * f + 3]);
                    mma_bf16(acc[mi][f][1], ah, blm[4 * f + 1], blm[4 * f + 3]);
                    mma_bf16(acc[mi][f][1], al, bhm[4 * f + 1], bhm[4 * f + 3]);
                }
            }
        }
    };

    issueStage(0);
    for (int s = 0; s < 4; s++) {
        if (s + 1 < 4) {
            issueStage(s + 1);
            CP_WAIT1();
        } else {
            CP_WAIT0();
        }
        __syncthreads();
        computeStage(s);
        __syncthreads();
    }

    float* sT = (float*)sm;
    const int dr = lane >> 2, dc = (lane & 3) * 2;
    for (int yw2 = 0; yw2 < 2; yw2++) {
        if (yw == yw2) {
#pragma unroll
            for (int mi = 0; mi < 4; mi++)
#pragma unroll
                for (int f = 0; f < 2; f++)
#pragma unroll
                    for (int ns = 0; ns < 2; ns++) {
                        int pix = m0w + mi * 16 + dr;
                        int c = n0 + f * 16 + ns * 8 + dc;
                        size_t i1 = (slab + pix) * Cn + mh * 128 + c;
                        size_t i2 = (slab + pix + 8) * Cn + mh * 128 + c;
                        float r0 = __bfloat162float(g_xch[i1])     + __bfloat162float(g_xcl[i1]);
                        float r1 = __bfloat162float(g_xch[i1 + 1]) + __bfloat162float(g_xcl[i1 + 1]);
                        float r2 = __bfloat162float(g_xch[i2])     + __bfloat162float(g_xcl[i2]);
                        float r3 = __bfloat162float(g_xch[i2 + 1]) + __bfloat162float(g_xcl[i2 + 1]);
                        int p = pix & 127;
                        sT[c * 132 + p]           = acc[mi][f][ns][0] + r0;
                        sT[(c + 1) * 132 + p]     = acc[mi][f][ns][1] + r1;
                        sT[c * 132 + p + 8]       = acc[mi][f][ns][2] + r2;
                        sT[(c + 1) * 132 + p + 8] = acc[mi][f][ns][3] + r3;
                    }
        }
        __syncthreads();
        for (int i = tid; i < 16384; i += 512) {
            int c = i >> 7, p = i & 127;
            out[(((size_t)b * 256 + mh * 128 + c) * Hn + yb * 2 + yw2) * Wn + p] = sT[c * 132 + p];
        }
        __syncthreads();
    }
}

// ---------------- launcher ----------------
extern "C" void kernel_launch(void* const* d_in, const int* in_sizes, int n_in,
                              void* d_out, int out_size) {
    const float* x   = (const float*)d_in[0];
    const float* c1w = (const float*)d_in[1];
    const float* c2w = (const float*)d_in[2];
    const float* mw1 = (const float*)d_in[3];
    const float* mb1 = (const float*)d_in[4];
    const float* mw2 = (const float*)d_in[5];
    const float* mb2 = (const float*)d_in[6];
    float* out = (float*)d_out;

    cudaFuncSetAttribute(conv1_tc, cudaFuncAttributeMaxDynamicSharedMemorySize, C1_SMEM);
    cudaFuncSetAttribute(conv2_tc, cudaFuncAttributeMaxDynamicSharedMemorySize, C2_SMEM);
    cudaFuncSetAttribute(attn_tc,  cudaFuncAttributeMaxDynamicSharedMemorySize, AT_SMEM);

    dummy_kernel<<<1, 32>>>();
    dummy_kernel<<<1, 32>>>();
    prep_kernel<<<288, 256>>>(c1w, c2w);
    conv1_tc<<<dim3(64, Bn), 512, C1_SMEM>>>(x);
    conv2_tc<<<dim3(64, 2, Bn), 512, C2_SMEM>>>();
    pool2_kernel<<<Bn, 256>>>();
    mlp_score_kernel<<<Bn, 256>>>(mw1, mb1, mw2, mb2);
    attn_tc<<<dim3(64, 2, Bn), 512, AT_SMEM>>>(out);
}